// round 16
// baseline (speedup 1.0000x reference)
#include <cuda_runtime.h>
#include <cuda_fp16.h>
#include <cstdint>

#define BATCH  4
#define SEQQ   2048
#define SEQK   2048
#define DMODEL 512
#define NH     8
#define DHEAD  64
#define NBH    (BATCH*NH)

// Q prescale: 1/sqrt(64) * log2(e)  (softmax runs in exp2 domain)
#define QSCALE 0.18033688011112042f

// ---------------- scratch (static device globals; no allocation) ----------------
__device__ __align__(16) __half g_qph[ (size_t)NBH*SEQQ*DHEAD ];   // [B,H,S,DH] fp16 (prescaled)
__device__ __align__(16) __half g_kph[ (size_t)NBH*SEQK*DHEAD ];
__device__ __align__(16) __half g_vph[ (size_t)NBH*SEQK*DHEAD ];
__device__ __align__(16) __half g_ctxh[ (size_t)BATCH*SEQQ*DMODEL ]; // [B,Q,D] fp16
__device__ __align__(16) __half g_wh [ (size_t)4*DMODEL*DMODEL ];    // fp16 weights (Wq*QSCALE, Wk, Wv, Wo)
__device__ __align__(16) __half g_xh [ (size_t)3*BATCH*SEQQ*DMODEL ];// fp16 inputs (q,k,v)

// =====================================================================
// helpers (sm_80+ path; compiles on compute_103)
// =====================================================================
__device__ __forceinline__ void mma_f16_16x8x16(float* d, const uint32_t* a,
                                                const uint32_t* b) {
    asm volatile(
        "mma.sync.aligned.m16n8k16.row.col.f32.f16.f16.f32 "
        "{%0,%1,%2,%3}, {%4,%5,%6,%7}, {%8,%9}, {%0,%1,%2,%3};"
        : "+f"(d[0]), "+f"(d[1]), "+f"(d[2]), "+f"(d[3])
        : "r"(a[0]), "r"(a[1]), "r"(a[2]), "r"(a[3]), "r"(b[0]), "r"(b[1]));
}

__device__ __forceinline__ void ldsm_x4(uint32_t* r, uint32_t addr) {
    asm volatile("ldmatrix.sync.aligned.m8n8.x4.shared.b16 {%0,%1,%2,%3}, [%4];"
                 : "=r"(r[0]), "=r"(r[1]), "=r"(r[2]), "=r"(r[3]) : "r"(addr));
}
__device__ __forceinline__ void ldsm_x4_trans(uint32_t* r, uint32_t addr) {
    asm volatile("ldmatrix.sync.aligned.m8n8.x4.trans.shared.b16 {%0,%1,%2,%3}, [%4];"
                 : "=r"(r[0]), "=r"(r[1]), "=r"(r[2]), "=r"(r[3]) : "r"(addr));
}

__device__ __forceinline__ uint32_t smem_u32(const void* p) {
    uint32_t a;
    asm("{ .reg .u64 t; cvta.to.shared.u64 t, %1; cvt.u32.u64 %0, t; }" : "=r"(a) : "l"(p));
    return a;
}

__device__ __forceinline__ uint32_t h2u(__half2 h) {
    return *reinterpret_cast<uint32_t*>(&h);
}

__device__ __forceinline__ float ex2(float x) {
    float y;
    asm("ex2.approx.ftz.f32 %0, %1;" : "=f"(y) : "f"(x));
    return y;
}
// packed fp16 exp2 on a half2 register
__device__ __forceinline__ uint32_t ex2_h2(uint32_t x) {
    asm("ex2.approx.f16x2 %0, %0;" : "+r"(x));
    return x;
}

__device__ __forceinline__ void cp16(uint32_t dst, const void* src) {
    asm volatile("cp.async.cg.shared.global [%0], [%1], 16;" :: "r"(dst), "l"(src));
}
#define CP_COMMIT() asm volatile("cp.async.commit_group;" ::: "memory")
#define CP_WAIT0()  asm volatile("cp.async.wait_group 0;"  ::: "memory")
#define CP_WAIT1()  asm volatile("cp.async.wait_group 1;"  ::: "memory")

// =====================================================================
// fp32 -> fp16 converter (weights + inputs), flat 1D grid:
// blocks [0,512): weights (4 x 128), blocks [512,6656): inputs (3 x 2048)
// =====================================================================
__global__ __launch_bounds__(256)
void cvt_all(const float* __restrict__ Xq, const float* __restrict__ Xk,
             const float* __restrict__ Xv,
             const float* __restrict__ Wq, const float* __restrict__ Wk,
             const float* __restrict__ Wv, const float* __restrict__ Wo)
{
    int id = blockIdx.x;
    const float* src; __half* dst; float scale = 1.f;
    size_t i;
    if (id < 512) {
        const int z = id >> 7;              // 0..3
        src = (z == 0) ? Wq : (z == 1) ? Wk : (z == 2) ? Wv : Wo;
        if (z == 0) scale = QSCALE;
        dst = g_wh + (size_t)z * DMODEL * DMODEL;
        i = ((size_t)(id & 127) * 256 + threadIdx.x) * 8;
    } else {
        id -= 512;
        const int z = id >> 11;             // 0..2
        src = (z == 0) ? Xq : (z == 1) ? Xk : Xv;
        dst = g_xh + (size_t)z * BATCH * SEQQ * DMODEL;
        i = ((size_t)(id & 2047) * 256 + threadIdx.x) * 8;
    }
    float4 x = *(const float4*)(src + i);
    float4 y = *(const float4*)(src + i + 4);
    uint4 u;
    u.x = h2u(__floats2half2_rn(x.x * scale, x.y * scale));
    u.y = h2u(__floats2half2_rn(x.z * scale, x.w * scale));
    u.z = h2u(__floats2half2_rn(y.x * scale, y.y * scale));
    u.w = h2u(__floats2half2_rn(y.z * scale, y.w * scale));
    *(uint4*)(dst + i) = u;
}

// =====================================================================
// all-fp16 HMMA GEMM: C[M,512] = A[M,512] @ W[N,512]^T
// 128x128 block tile, 8 warps (2x4), warp tile 64x32.
// BK=32 chunks, 3-stage cp.async pipeline. smem 48 KB static.
// HOUT=1: fp16 scatter to [B,H,S,DH]; HOUT=0: fp32 [M,N].
// =====================================================================
template<int HOUT>
__device__ __forceinline__ void gemm_h_body(const __half* __restrict__ A,
                                            const __half* __restrict__ W,
                                            void* __restrict__ Cv)
{
    __shared__ __align__(16) __half sA[3][128 * 32];   // 3 x 8 KB
    __shared__ __align__(16) __half sB[3][128 * 32];   // 3 x 8 KB

    const int tid  = threadIdx.x;
    const int wid  = tid >> 5;
    const int lane = tid & 31;
    const int m0   = blockIdx.y * 128;
    const int n0   = blockIdx.x * 128;

    const int warp_m = wid >> 2;
    const int warp_n = wid & 3;
    const int g  = lane >> 2;
    const int t  = lane & 3;
    const int mm = lane >> 3;
    const int r8 = lane & 7;

    const uint32_t sAb = smem_u32(sA);
    const uint32_t sBb = smem_u32(sB);
    const uint32_t axor = (uint32_t)((r8 >> 1) & 3);
    const uint32_t a_base = sAb + (uint32_t)(warp_m * 64 + ((mm & 1) << 3) + r8) * 64;
    const uint32_t b_base = sBb + (uint32_t)(warp_n * 32 + ((mm >> 1) << 3) + r8) * 64;

    const int row0 = tid >> 2,           c0 = tid & 3;
    const int row1 = (tid + 256) >> 2,   c1 = (tid + 256) & 3;
    const uint32_t d0 = (uint32_t)(row0 * 64 + (((uint32_t)c0 ^ ((row0 >> 1) & 3)) << 4));
    const uint32_t d1 = (uint32_t)(row1 * 64 + (((uint32_t)c1 ^ ((row1 >> 1) & 3)) << 4));
    const __half* Ag0 = A + (size_t)(m0 + row0) * DMODEL + c0 * 8;
    const __half* Ag1 = A + (size_t)(m0 + row1) * DMODEL + c1 * 8;
    const __half* Wg0 = W + (size_t)(n0 + row0) * DMODEL + c0 * 8;
    const __half* Wg1 = W + (size_t)(n0 + row1) * DMODEL + c1 * 8;

    float acc[4][4][4];
#pragma unroll
    for (int mi = 0; mi < 4; mi++)
#pragma unroll
        for (int ni = 0; ni < 4; ni++)
#pragma unroll
            for (int f = 0; f < 4; f++) acc[mi][ni][f] = 0.f;

    // prologue: stage chunks 0,1 into buffers 0,1
#pragma unroll
    for (int p = 0; p < 2; p++) {
        const uint32_t ob = (uint32_t)p * 8192;
        const int kk = p << 5;
        cp16(sAb + ob + d0, Ag0 + kk); cp16(sAb + ob + d1, Ag1 + kk);
        cp16(sBb + ob + d0, Wg0 + kk); cp16(sBb + ob + d1, Wg1 + kk);
        CP_COMMIT();
    }

    for (int ch = 0; ch < 16; ++ch) {
        const uint32_t bofs = (uint32_t)(ch % 3) * 8192;

        CP_WAIT1();          // chunk ch landed (ch+1 may still be in flight)
        __syncthreads();

        if (ch + 2 < 16) {
            const uint32_t ob = (uint32_t)((ch + 2) % 3) * 8192;
            const int kk = (ch + 2) << 5;
            cp16(sAb + ob + d0, Ag0 + kk); cp16(sAb + ob + d1, Ag1 + kk);
            cp16(sBb + ob + d0, Wg0 + kk); cp16(sBb + ob + d1, Wg1 + kk);
        }
        CP_COMMIT();         // always commit (empty groups keep the count in step)

#pragma unroll
        for (int ks = 0; ks < 2; ks++) {
            uint32_t af[4][4];
            const uint32_t ac = ((((uint32_t)(ks << 1) | (uint32_t)(mm >> 1)) ^ axor) << 4);
#pragma unroll
            for (int mi = 0; mi < 4; mi++)
                ldsm_x4(af[mi], a_base + bofs + ((uint32_t)mi << 10) + ac);
            uint32_t bf[2][4];
            const uint32_t bc = ((((uint32_t)(ks << 1) | (uint32_t)(mm & 1)) ^ axor) << 4);
#pragma unroll
            for (int nfp = 0; nfp < 2; nfp++)
                ldsm_x4(bf[nfp], b_base + bofs + ((uint32_t)nfp << 10) + bc);
#pragma unroll
            for (int mi = 0; mi < 4; mi++)
#pragma unroll
                for (int nfp = 0; nfp < 2; nfp++) {
                    mma_f16_16x8x16(acc[mi][2 * nfp    ], af[mi], bf[nfp]    );
                    mma_f16_16x8x16(acc[mi][2 * nfp + 1], af[mi], bf[nfp] + 2);
                }
        }
    }

#pragma unroll
    for (int mi = 0; mi < 4; mi++) {
#pragma unroll
        for (int ni = 0; ni < 4; ni++) {
            const int row = m0 + warp_m * 64 + mi * 16 + g;
            const int col = n0 + warp_n * 32 + ni * 8 + t * 2;
            if (HOUT) {
                __half* Ch = (__half*)Cv;
                const int b = row >> 11, s = row & 2047;
                const int hh = col >> 6, dh = col & 63;
                size_t o0 = ((((size_t)b * NH + hh) * SEQQ + s) << 6) + dh;
                *(__half2*)(Ch + o0) =
                    __floats2half2_rn(acc[mi][ni][0], acc[mi][ni][1]);
                *(__half2*)(Ch + o0 + ((size_t)8 << 6)) =
                    __floats2half2_rn(acc[mi][ni][2], acc[mi][ni][3]);
            } else {
                float* Cf = (float*)Cv;
                size_t o0 = (size_t)row * DMODEL + col;
                *(float2*)(Cf + o0) = make_float2(acc[mi][ni][0], acc[mi][ni][1]);
                *(float2*)(Cf + o0 + (size_t)8 * DMODEL) =
                    make_float2(acc[mi][ni][2], acc[mi][ni][3]);
            }
        }
    }
}

// Fused Q/K/V projections (blockIdx.z selects GEMM).
__global__ __launch_bounds__(256, 2)
void gemm_qkv(__half* __restrict__ Cq, __half* __restrict__ Ck,
              __half* __restrict__ Cv)
{
    const int z = blockIdx.z;
    const __half* A = g_xh + (size_t)z * BATCH * SEQQ * DMODEL;
    const __half* W = g_wh + (size_t)z * DMODEL * DMODEL;
    __half* C = (z == 0) ? Cq : (z == 1) ? Ck : Cv;
    gemm_h_body<1>(A, W, C);
}

__global__ __launch_bounds__(256, 2)
void gemm_out(const __half* __restrict__ ctx, float* __restrict__ out)
{
    gemm_h_body<0>(ctx, g_wh + (size_t)3 * DMODEL * DMODEL, out);
}

// =====================================================================
// Flash attention: fp16 mma + ldmatrix + 3-stage cp.async K/V pipeline.
// Block: 128 queries x one (b,h); batch interleaved across blockIdx.y
// (b = y&3) so heavy batches spread evenly over the 1.7-wave launch.
// Softmax: packed fp16 exp2; l via ones-MMA.
// =====================================================================
__global__ __launch_bounds__(256, 2)
void flash_attn(const int* __restrict__ valid_lens, __half* __restrict__ ctx)
{
    __shared__ __align__(16) __half sK[3][64 * 64];   // 3 x 8 KB
    __shared__ __align__(16) __half sV[3][64 * 64];   // 3 x 8 KB

    const int tid  = threadIdx.x;
    const int wr   = tid >> 5;
    const int lane = tid & 31;
    const int g    = lane >> 2;
    const int t    = lane & 3;

    const int by = blockIdx.y;          // 0..31
    const int b  = by & 3;              // batch varies fastest -> wave balance
    const int h  = by >> 2;
    const int bh = b * NH + h;
    const int q0 = blockIdx.x << 7;     // BQ = 128
    const int valid = valid_lens[b];

    const __half* Qw = g_qph + ((size_t)bh * SEQQ + q0 + wr * 16) * DHEAD;
    const __half* Kb = g_kph + (size_t)bh * SEQK * DHEAD;
    const __half* Vb = g_vph + (size_t)bh * SEQK * DHEAD;

    uint32_t qf[4][4];
#pragma unroll
    for (int j = 0; j < 4; j++) {
        qf[j][0] = *(const uint32_t*)(Qw + (g    ) * 64 + j * 16 + 2 * t);
        qf[j][1] = *(const uint32_t*)(Qw + (g + 8) * 64 + j * 16 + 2 * t);
        qf[j][2] = *(const uint32_t*)(Qw + (g    ) * 64 + j * 16 + 8 + 2 * t);
        qf[j][3] = *(const uint32_t*)(Qw + (g + 8) * 64 + j * 16 + 8 + 2 * t);
    }

    const int k0s = tid >> 3,         c0s = tid & 7;
    const int k1s = (tid + 256) >> 3, c1s = (tid + 256) & 7;
    const uint32_t off0 = (uint32_t)(k0s * 128 + (((uint32_t)c0s << 4) ^ ((k0s & 7) << 4)));
    const uint32_t off1 = (uint32_t)(k1s * 128 + (((uint32_t)c1s << 4) ^ ((k1s & 7) << 4)));
    const size_t gm0 = (size_t)k0s * 64 + c0s * 8;
    const size_t gm1 = (size_t)k1s * 64 + c1s * 8;

    const uint32_t skb = smem_u32(sK);
    const uint32_t svb = smem_u32(sV);
    const int m  = lane >> 3;
    const int r8 = lane & 7;
    const uint32_t xr = (uint32_t)r8 << 4;
    const uint32_t k_rowbase = skb + (uint32_t)(((m >> 1) << 3) + r8) * 128;
    const uint32_t k_cbit    = (uint32_t)(m & 1) << 4;
    const uint32_t v_rowbase = svb + (uint32_t)(((m & 1) << 3) + r8) * 128;
    const uint32_t v_cbit    = (uint32_t)(m >> 1) << 4;

    const uint32_t ones2 = 0x3C003C00u;           // half2(1,1)
    const uint32_t onesfrag[2] = { ones2, ones2 };

    float m0 = -1e30f, m1 = -1e30f;
    float l_acc[4] = {0.f, 0.f, 0.f, 0.f};
    float o[8][4];
#pragma unroll
    for (int nf = 0; nf < 8; nf++)
#pragma unroll
        for (int f = 0; f < 4; f++) o[nf][f] = 0.f;

    const int nTiles = (valid + 63) >> 6;

    // ---- prologue: stage tiles 0 (and 1) into buffers 0,1 ----
    cp16(skb + off0, Kb + gm0); cp16(skb + off1, Kb + gm1);
    cp16(svb + off0, Vb + gm0); cp16(svb + off1, Vb + gm1);
    CP_COMMIT();
    if (nTiles > 1) {
        const __half* Kt = Kb + 64 * 64;
        const __half* Vt = Vb + 64 * 64;
        cp16(skb + 8192 + off0, Kt + gm0); cp16(skb + 8192 + off1, Kt + gm1);
        cp16(svb + 8192 + off0, Vt + gm0); cp16(svb + 8192 + off1, Vt + gm1);
    }
    CP_COMMIT();

    for (int tt = 0; tt < nTiles; tt++) {
        const uint32_t bofs = (uint32_t)(tt % 3) << 13;

        CP_WAIT1();          // tile tt landed (tt+1 may still be in flight)
        __syncthreads();

        if (tt + 2 < nTiles) {
            const uint32_t ob = (uint32_t)((tt + 2) % 3) << 13;
            const __half* Kt = Kb + (size_t)(tt + 2) * 64 * 64;
            const __half* Vt = Vb + (size_t)(tt + 2) * 64 * 64;
            cp16(skb + ob + off0, Kt + gm0); cp16(skb + ob + off1, Kt + gm1);
            cp16(svb + ob + off0, Vt + gm0); cp16(svb + ob + off1, Vt + gm1);
        }
        CP_COMMIT();         // always commit (keeps group count in step)

        const int kbase = tt << 6;

        // ---- S = Q K^T (log2-scaled) ----
        float sc[8][4];
#pragma unroll
        for (int nf = 0; nf < 8; nf++)
#pragma unroll
            for (int f = 0; f < 4; f++) sc[nf][f] = 0.f;

#pragma unroll
        for (int ks = 0; ks < 4; ks++) {
            const uint32_t koff = (((uint32_t)ks << 5) | k_cbit) ^ xr;
#pragma unroll
            for (int nfp = 0; nfp < 4; nfp++) {
                uint32_t r[4];
                ldsm_x4(r, k_rowbase + bofs + ((uint32_t)nfp << 11) + koff);
                mma_f16_16x8x16(sc[2 * nfp    ], qf[ks], r    );
                mma_f16_16x8x16(sc[2 * nfp + 1], qf[ks], r + 2);
            }
        }

        // ---- mask tail columns ----
        if (kbase + 64 > valid) {
#pragma unroll
            for (int nf = 0; nf < 8; nf++) {
                const int c0 = kbase + nf * 8 + 2 * t;
                if (c0     >= valid) { sc[nf][0] = -1e30f; sc[nf][2] = -1e30f; }
                if (c0 + 1 >= valid) { sc[nf][1] = -1e30f; sc[nf][3] = -1e30f; }
            }
        }

        // ---- online softmax (packed fp16 exp2) ----
        float mx0 = -1e30f, mx1 = -1e30f;
#pragma unroll
        for (int nf = 0; nf < 8; nf++) {
            mx0 = fmaxf(mx0, fmaxf(sc[nf][0], sc[nf][1]));
            mx1 = fmaxf(mx1, fmaxf(sc[nf][2], sc[nf][3]));
        }
        mx0 = fmaxf(mx0, __shfl_xor_sync(0xffffffffu, mx0, 1));
        mx0 = fmaxf(mx0, __shfl_xor_sync(0xffffffffu, mx0, 2));
        mx1 = fmaxf(mx1, __shfl_xor_sync(0xffffffffu, mx1, 1));
        mx1 = fmaxf(mx1, __shfl_xor_sync(0xffffffffu, mx1, 2));

        const float m0n = fmaxf(m0, mx0);
        const float m1n = fmaxf(m1, mx1);
        const float s0  = ex2(m0 - m0n);
        const float s1  = ex2(m1 - m1n);
        m0 = m0n; m1 = m1n;

        uint32_t pf[8][2];
#pragma unroll
        for (int nf = 0; nf < 8; nf++) {
            pf[nf][0] = ex2_h2(h2u(__floats2half2_rn(sc[nf][0] - m0n, sc[nf][1] - m0n)));
            pf[nf][1] = ex2_h2(h2u(__floats2half2_rn(sc[nf][2] - m1n, sc[nf][3] - m1n)));
        }
        l_acc[0] *= s0; l_acc[1] *= s0; l_acc[2] *= s1; l_acc[3] *= s1;
#pragma unroll
        for (int nf = 0; nf < 8; nf++) {
            o[nf][0] *= s0; o[nf][1] *= s0;
            o[nf][2] *= s1; o[nf][3] *= s1;
        }

        // ---- O += P V ; l += P 1 ----
#pragma unroll
        for (int ks = 0; ks < 4; ks++) {
            uint32_t af[4];
            af[0] = pf[2 * ks][0];
            af[1] = pf[2 * ks][1];
            af[2] = pf[2 * ks + 1][0];
            af[3] = pf[2 * ks + 1][1];
            mma_f16_16x8x16(l_acc, af, onesfrag);
            const uint32_t vrow = v_rowbase + bofs + ((uint32_t)ks << 11);
#pragma unroll
            for (int nfp = 0; nfp < 4; nfp++) {
                uint32_t r[4];
                ldsm_x4_trans(r, vrow + ((((uint32_t)nfp << 5) + v_cbit) ^ xr));
                mma_f16_16x8x16(o[2 * nfp    ], af, r    );
                mma_f16_16x8x16(o[2 * nfp + 1], af, r + 2);
            }
        }
    }

    // ---- epilogue (l already row-complete; no shfl needed) ----
    const float i0 = 1.f / l_acc[0];
    const float i1 = 1.f / l_acc[2];

    const int row0 = q0 + wr * 16 + g;
    __half* out0 = ctx + ((size_t)b * SEQQ + row0) * DMODEL + h * DHEAD;
    __half* out1 = out0 + (size_t)8 * DMODEL;
#pragma unroll
    for (int nf = 0; nf < 8; nf++) {
        const int col = nf * 8 + 2 * t;
        *(__half2*)(out0 + col) = __floats2half2_rn(o[nf][0] * i0, o[nf][1] * i0);
        *(__half2*)(out1 + col) = __floats2half2_rn(o[nf][2] * i1, o[nf][3] * i1);
    }
}

// =====================================================================
// launch
// =====================================================================
extern "C" void kernel_launch(void* const* d_in, const int* in_sizes, int n_in,
                              void* d_out, int out_size)
{
    const float* queries    = (const float*)d_in[0];
    const float* keys       = (const float*)d_in[1];
    const float* values     = (const float*)d_in[2];
    const int*   valid_lens = (const int*)  d_in[3];
    const float* W_q        = (const float*)d_in[4];
    const float* W_k        = (const float*)d_in[5];
    const float* W_v        = (const float*)d_in[6];
    const float* W_o        = (const float*)d_in[7];

    void *qp, *kp, *vp, *ctx;
    cudaGetSymbolAddress(&qp,  g_qph);
    cudaGetSymbolAddress(&kp,  g_kph);
    cudaGetSymbolAddress(&vp,  g_vph);
    cudaGetSymbolAddress(&ctx, g_ctxh);

    // pre-convert weights + inputs to fp16 (QSCALE folded into W_q)
    cvt_all<<<6656, 256>>>(queries, keys, values, W_q, W_k, W_v, W_o);

    dim3 gridQKV(DMODEL / 128, (BATCH * SEQQ) / 128, 3);   // (4, 64, 3)
    gemm_qkv<<<gridQKV, 256>>>((__half*)qp, (__half*)kp, (__half*)vp);

    dim3 gridF(SEQQ / 128, NBH);                           // (16, 32)
    flash_attn<<<gridF, 256>>>(valid_lens, (__half*)ctx);

    dim3 gridO(DMODEL / 128, (BATCH * SEQQ) / 128);        // (4, 64)
    gemm_out<<<gridO, 256>>>((const __half*)ctx, (float*)d_out);
}

// round 17
// speedup vs baseline: 1.0199x; 1.0199x over previous
#include <cuda_runtime.h>
#include <cuda_fp16.h>
#include <cstdint>

#define BATCH  4
#define SEQQ   2048
#define SEQK   2048
#define DMODEL 512
#define NH     8
#define DHEAD  64
#define NBH    (BATCH*NH)

// Q prescale: 1/sqrt(64) * log2(e)  (softmax runs in exp2 domain)
#define QSCALE 0.18033688011112042f

// ---------------- scratch (static device globals; no allocation) ----------------
__device__ __align__(16) __half g_qph[ (size_t)NBH*SEQQ*DHEAD ];   // [B,H,S,DH] fp16 (prescaled)
__device__ __align__(16) __half g_kph[ (size_t)NBH*SEQK*DHEAD ];
__device__ __align__(16) __half g_vph[ (size_t)NBH*SEQK*DHEAD ];
__device__ __align__(16) __half g_ctxh[ (size_t)BATCH*SEQQ*DMODEL ]; // [B,Q,D] fp16
__device__ __align__(16) __half g_wh [ (size_t)4*DMODEL*DMODEL ];    // fp16 weights (Wq*QSCALE, Wk, Wv, Wo)
__device__ __align__(16) __half g_xh [ (size_t)3*BATCH*SEQQ*DMODEL ];// fp16 inputs (q,k,v)

// =====================================================================
// helpers (sm_80+ path; compiles on compute_103)
// =====================================================================
__device__ __forceinline__ void mma_f16_16x8x16(float* d, const uint32_t* a,
                                                const uint32_t* b) {
    asm volatile(
        "mma.sync.aligned.m16n8k16.row.col.f32.f16.f16.f32 "
        "{%0,%1,%2,%3}, {%4,%5,%6,%7}, {%8,%9}, {%0,%1,%2,%3};"
        : "+f"(d[0]), "+f"(d[1]), "+f"(d[2]), "+f"(d[3])
        : "r"(a[0]), "r"(a[1]), "r"(a[2]), "r"(a[3]), "r"(b[0]), "r"(b[1]));
}

__device__ __forceinline__ void ldsm_x4(uint32_t* r, uint32_t addr) {
    asm volatile("ldmatrix.sync.aligned.m8n8.x4.shared.b16 {%0,%1,%2,%3}, [%4];"
                 : "=r"(r[0]), "=r"(r[1]), "=r"(r[2]), "=r"(r[3]) : "r"(addr));
}
__device__ __forceinline__ void ldsm_x4_trans(uint32_t* r, uint32_t addr) {
    asm volatile("ldmatrix.sync.aligned.m8n8.x4.trans.shared.b16 {%0,%1,%2,%3}, [%4];"
                 : "=r"(r[0]), "=r"(r[1]), "=r"(r[2]), "=r"(r[3]) : "r"(addr));
}

__device__ __forceinline__ uint32_t smem_u32(const void* p) {
    uint32_t a;
    asm("{ .reg .u64 t; cvta.to.shared.u64 t, %1; cvt.u32.u64 %0, t; }" : "=r"(a) : "l"(p));
    return a;
}

__device__ __forceinline__ uint32_t h2u(__half2 h) {
    return *reinterpret_cast<uint32_t*>(&h);
}
__device__ __forceinline__ __half2 u2h(uint32_t u) {
    return *reinterpret_cast<__half2*>(&u);
}

__device__ __forceinline__ float ex2(float x) {
    float y;
    asm("ex2.approx.ftz.f32 %0, %1;" : "=f"(y) : "f"(x));
    return y;
}
// packed fp16 exp2 on a half2 register
__device__ __forceinline__ uint32_t ex2_h2(uint32_t x) {
    asm("ex2.approx.f16x2 %0, %0;" : "+r"(x));
    return x;
}

__device__ __forceinline__ void cp16(uint32_t dst, const void* src) {
    asm volatile("cp.async.cg.shared.global [%0], [%1], 16;" :: "r"(dst), "l"(src));
}
#define CP_COMMIT() asm volatile("cp.async.commit_group;" ::: "memory")
#define CP_WAIT0()  asm volatile("cp.async.wait_group 0;"  ::: "memory")
#define CP_WAIT1()  asm volatile("cp.async.wait_group 1;"  ::: "memory")

// =====================================================================
// fp32 -> fp16 converter (weights + inputs), flat 1D grid:
// blocks [0,512): weights (4 x 128), blocks [512,6656): inputs (3 x 2048)
// =====================================================================
__global__ __launch_bounds__(256)
void cvt_all(const float* __restrict__ Xq, const float* __restrict__ Xk,
             const float* __restrict__ Xv,
             const float* __restrict__ Wq, const float* __restrict__ Wk,
             const float* __restrict__ Wv, const float* __restrict__ Wo)
{
    int id = blockIdx.x;
    const float* src; __half* dst; float scale = 1.f;
    size_t i;
    if (id < 512) {
        const int z = id >> 7;              // 0..3
        src = (z == 0) ? Wq : (z == 1) ? Wk : (z == 2) ? Wv : Wo;
        if (z == 0) scale = QSCALE;
        dst = g_wh + (size_t)z * DMODEL * DMODEL;
        i = ((size_t)(id & 127) * 256 + threadIdx.x) * 8;
    } else {
        id -= 512;
        const int z = id >> 11;             // 0..2
        src = (z == 0) ? Xq : (z == 1) ? Xk : Xv;
        dst = g_xh + (size_t)z * BATCH * SEQQ * DMODEL;
        i = ((size_t)(id & 2047) * 256 + threadIdx.x) * 8;
    }
    float4 x = *(const float4*)(src + i);
    float4 y = *(const float4*)(src + i + 4);
    uint4 u;
    u.x = h2u(__floats2half2_rn(x.x * scale, x.y * scale));
    u.y = h2u(__floats2half2_rn(x.z * scale, x.w * scale));
    u.z = h2u(__floats2half2_rn(y.x * scale, y.y * scale));
    u.w = h2u(__floats2half2_rn(y.z * scale, y.w * scale));
    *(uint4*)(dst + i) = u;
}

// =====================================================================
// all-fp16 HMMA GEMM: C[M,512] = A[M,512] @ W[N,512]^T
// 128x128 block tile, 8 warps (2x4), warp tile 64x32.
// BK=32 chunks, 3-stage cp.async pipeline. smem 48 KB static.
// HOUT=1: fp16 scatter to [B,H,S,DH]; HOUT=0: fp32 [M,N].
// =====================================================================
template<int HOUT>
__device__ __forceinline__ void gemm_h_body(const __half* __restrict__ A,
                                            const __half* __restrict__ W,
                                            void* __restrict__ Cv)
{
    __shared__ __align__(16) __half sA[3][128 * 32];   // 3 x 8 KB
    __shared__ __align__(16) __half sB[3][128 * 32];   // 3 x 8 KB

    const int tid  = threadIdx.x;
    const int wid  = tid >> 5;
    const int lane = tid & 31;
    const int m0   = blockIdx.y * 128;
    const int n0   = blockIdx.x * 128;

    const int warp_m = wid >> 2;
    const int warp_n = wid & 3;
    const int g  = lane >> 2;
    const int t  = lane & 3;
    const int mm = lane >> 3;
    const int r8 = lane & 7;

    const uint32_t sAb = smem_u32(sA);
    const uint32_t sBb = smem_u32(sB);
    const uint32_t axor = (uint32_t)((r8 >> 1) & 3);
    const uint32_t a_base = sAb + (uint32_t)(warp_m * 64 + ((mm & 1) << 3) + r8) * 64;
    const uint32_t b_base = sBb + (uint32_t)(warp_n * 32 + ((mm >> 1) << 3) + r8) * 64;

    const int row0 = tid >> 2,           c0 = tid & 3;
    const int row1 = (tid + 256) >> 2,   c1 = (tid + 256) & 3;
    const uint32_t d0 = (uint32_t)(row0 * 64 + (((uint32_t)c0 ^ ((row0 >> 1) & 3)) << 4));
    const uint32_t d1 = (uint32_t)(row1 * 64 + (((uint32_t)c1 ^ ((row1 >> 1) & 3)) << 4));
    const __half* Ag0 = A + (size_t)(m0 + row0) * DMODEL + c0 * 8;
    const __half* Ag1 = A + (size_t)(m0 + row1) * DMODEL + c1 * 8;
    const __half* Wg0 = W + (size_t)(n0 + row0) * DMODEL + c0 * 8;
    const __half* Wg1 = W + (size_t)(n0 + row1) * DMODEL + c1 * 8;

    float acc[4][4][4];
#pragma unroll
    for (int mi = 0; mi < 4; mi++)
#pragma unroll
        for (int ni = 0; ni < 4; ni++)
#pragma unroll
            for (int f = 0; f < 4; f++) acc[mi][ni][f] = 0.f;

    // prologue: stage chunks 0,1 into buffers 0,1
#pragma unroll
    for (int p = 0; p < 2; p++) {
        const uint32_t ob = (uint32_t)p * 8192;
        const int kk = p << 5;
        cp16(sAb + ob + d0, Ag0 + kk); cp16(sAb + ob + d1, Ag1 + kk);
        cp16(sBb + ob + d0, Wg0 + kk); cp16(sBb + ob + d1, Wg1 + kk);
        CP_COMMIT();
    }

    for (int ch = 0; ch < 16; ++ch) {
        const uint32_t bofs = (uint32_t)(ch % 3) * 8192;

        CP_WAIT1();          // chunk ch landed (ch+1 may still be in flight)
        __syncthreads();

        if (ch + 2 < 16) {
            const uint32_t ob = (uint32_t)((ch + 2) % 3) * 8192;
            const int kk = (ch + 2) << 5;
            cp16(sAb + ob + d0, Ag0 + kk); cp16(sAb + ob + d1, Ag1 + kk);
            cp16(sBb + ob + d0, Wg0 + kk); cp16(sBb + ob + d1, Wg1 + kk);
        }
        CP_COMMIT();         // always commit (empty groups keep the count in step)

#pragma unroll
        for (int ks = 0; ks < 2; ks++) {
            uint32_t af[4][4];
            const uint32_t ac = ((((uint32_t)(ks << 1) | (uint32_t)(mm >> 1)) ^ axor) << 4);
#pragma unroll
            for (int mi = 0; mi < 4; mi++)
                ldsm_x4(af[mi], a_base + bofs + ((uint32_t)mi << 10) + ac);
            uint32_t bf[2][4];
            const uint32_t bc = ((((uint32_t)(ks << 1) | (uint32_t)(mm & 1)) ^ axor) << 4);
#pragma unroll
            for (int nfp = 0; nfp < 2; nfp++)
                ldsm_x4(bf[nfp], b_base + bofs + ((uint32_t)nfp << 10) + bc);
#pragma unroll
            for (int mi = 0; mi < 4; mi++)
#pragma unroll
                for (int nfp = 0; nfp < 2; nfp++) {
                    mma_f16_16x8x16(acc[mi][2 * nfp    ], af[mi], bf[nfp]    );
                    mma_f16_16x8x16(acc[mi][2 * nfp + 1], af[mi], bf[nfp] + 2);
                }
        }
    }

#pragma unroll
    for (int mi = 0; mi < 4; mi++) {
#pragma unroll
        for (int ni = 0; ni < 4; ni++) {
            const int row = m0 + warp_m * 64 + mi * 16 + g;
            const int col = n0 + warp_n * 32 + ni * 8 + t * 2;
            if (HOUT) {
                __half* Ch = (__half*)Cv;
                const int b = row >> 11, s = row & 2047;
                const int hh = col >> 6, dh = col & 63;
                size_t o0 = ((((size_t)b * NH + hh) * SEQQ + s) << 6) + dh;
                *(__half2*)(Ch + o0) =
                    __floats2half2_rn(acc[mi][ni][0], acc[mi][ni][1]);
                *(__half2*)(Ch + o0 + ((size_t)8 << 6)) =
                    __floats2half2_rn(acc[mi][ni][2], acc[mi][ni][3]);
            } else {
                float* Cf = (float*)Cv;
                size_t o0 = (size_t)row * DMODEL + col;
                *(float2*)(Cf + o0) = make_float2(acc[mi][ni][0], acc[mi][ni][1]);
                *(float2*)(Cf + o0 + (size_t)8 * DMODEL) =
                    make_float2(acc[mi][ni][2], acc[mi][ni][3]);
            }
        }
    }
}

// Fused Q/K/V projections (blockIdx.z selects GEMM).
__global__ __launch_bounds__(256, 2)
void gemm_qkv(__half* __restrict__ Cq, __half* __restrict__ Ck,
              __half* __restrict__ Cv)
{
    const int z = blockIdx.z;
    const __half* A = g_xh + (size_t)z * BATCH * SEQQ * DMODEL;
    const __half* W = g_wh + (size_t)z * DMODEL * DMODEL;
    __half* C = (z == 0) ? Cq : (z == 1) ? Ck : Cv;
    gemm_h_body<1>(A, W, C);
}

__global__ __launch_bounds__(256, 2)
void gemm_out(const __half* __restrict__ ctx, float* __restrict__ out)
{
    gemm_h_body<0>(ctx, g_wh + (size_t)3 * DMODEL * DMODEL, out);
}

// =====================================================================
// Flash attention: fp16 mma + ldmatrix + 2-stage cp.async K/V pipeline
// (exact R15 structure). Softmax: packed fp16 exp2. l: per-thread fp32
// partials fed by a half2 HADD2 tree over pf (fma pipe, not tensor pipe),
// 4-lane shfl reduction once at the end.
// =====================================================================
__global__ __launch_bounds__(256, 2)
void flash_attn(const int* __restrict__ valid_lens, __half* __restrict__ ctx)
{
    __shared__ __align__(16) __half sK[2][64 * 64];   // 2 x 8 KB
    __shared__ __align__(16) __half sV[2][64 * 64];   // 2 x 8 KB

    const int tid  = threadIdx.x;
    const int wr   = tid >> 5;
    const int lane = tid & 31;
    const int g    = lane >> 2;
    const int t    = lane & 3;

    const int bh = blockIdx.y;
    const int b  = bh >> 3;
    const int h  = bh & 7;
    const int q0 = blockIdx.x << 7;     // BQ = 128
    const int valid = valid_lens[b];

    const __half* Qw = g_qph + ((size_t)bh * SEQQ + q0 + wr * 16) * DHEAD;
    const __half* Kb = g_kph + (size_t)bh * SEQK * DHEAD;
    const __half* Vb = g_vph + (size_t)bh * SEQK * DHEAD;

    uint32_t qf[4][4];
#pragma unroll
    for (int j = 0; j < 4; j++) {
        qf[j][0] = *(const uint32_t*)(Qw + (g    ) * 64 + j * 16 + 2 * t);
        qf[j][1] = *(const uint32_t*)(Qw + (g + 8) * 64 + j * 16 + 2 * t);
        qf[j][2] = *(const uint32_t*)(Qw + (g    ) * 64 + j * 16 + 8 + 2 * t);
        qf[j][3] = *(const uint32_t*)(Qw + (g + 8) * 64 + j * 16 + 8 + 2 * t);
    }

    const int k0s = tid >> 3,         c0s = tid & 7;
    const int k1s = (tid + 256) >> 3, c1s = (tid + 256) & 7;
    const uint32_t off0 = (uint32_t)(k0s * 128 + (((uint32_t)c0s << 4) ^ ((k0s & 7) << 4)));
    const uint32_t off1 = (uint32_t)(k1s * 128 + (((uint32_t)c1s << 4) ^ ((k1s & 7) << 4)));
    const size_t gm0 = (size_t)k0s * 64 + c0s * 8;
    const size_t gm1 = (size_t)k1s * 64 + c1s * 8;

    const uint32_t skb = smem_u32(sK);
    const uint32_t svb = smem_u32(sV);
    const int m  = lane >> 3;
    const int r8 = lane & 7;
    const uint32_t xr = (uint32_t)r8 << 4;
    const uint32_t k_rowbase = skb + (uint32_t)(((m >> 1) << 3) + r8) * 128;
    const uint32_t k_cbit    = (uint32_t)(m & 1) << 4;
    const uint32_t v_rowbase = svb + (uint32_t)(((m & 1) << 3) + r8) * 128;
    const uint32_t v_cbit    = (uint32_t)(m >> 1) << 4;

    float m0 = -1e30f, m1 = -1e30f;
    float l0 = 0.f,    l1 = 0.f;        // per-thread partials (reduced at end)
    float o[8][4];
#pragma unroll
    for (int nf = 0; nf < 8; nf++)
#pragma unroll
        for (int f = 0; f < 4; f++) o[nf][f] = 0.f;

    const int nTiles = (valid + 63) >> 6;

    {
        cp16(skb + off0, Kb + gm0); cp16(skb + off1, Kb + gm1);
        cp16(svb + off0, Vb + gm0); cp16(svb + off1, Vb + gm1);
        CP_COMMIT();
    }

    for (int tt = 0; tt < nTiles; tt++) {
        const int buf = tt & 1;
        const uint32_t bofs = (uint32_t)buf << 13;

        CP_WAIT0();
        __syncthreads();

        if (tt + 1 < nTiles) {
            const uint32_t ob = (uint32_t)(buf ^ 1) << 13;
            const __half* Kt = Kb + (size_t)(tt + 1) * 64 * 64;
            const __half* Vt = Vb + (size_t)(tt + 1) * 64 * 64;
            cp16(skb + ob + off0, Kt + gm0); cp16(skb + ob + off1, Kt + gm1);
            cp16(svb + ob + off0, Vt + gm0); cp16(svb + ob + off1, Vt + gm1);
            CP_COMMIT();
        }

        const int kbase = tt << 6;

        // ---- S = Q K^T (log2-scaled) ----
        float sc[8][4];
#pragma unroll
        for (int nf = 0; nf < 8; nf++)
#pragma unroll
            for (int f = 0; f < 4; f++) sc[nf][f] = 0.f;

#pragma unroll
        for (int ks = 0; ks < 4; ks++) {
            const uint32_t koff = (((uint32_t)ks << 5) | k_cbit) ^ xr;
#pragma unroll
            for (int nfp = 0; nfp < 4; nfp++) {
                uint32_t r[4];
                ldsm_x4(r, k_rowbase + bofs + ((uint32_t)nfp << 11) + koff);
                mma_f16_16x8x16(sc[2 * nfp    ], qf[ks], r    );
                mma_f16_16x8x16(sc[2 * nfp + 1], qf[ks], r + 2);
            }
        }

        // ---- mask tail columns ----
        if (kbase + 64 > valid) {
#pragma unroll
            for (int nf = 0; nf < 8; nf++) {
                const int c0 = kbase + nf * 8 + 2 * t;
                if (c0     >= valid) { sc[nf][0] = -1e30f; sc[nf][2] = -1e30f; }
                if (c0 + 1 >= valid) { sc[nf][1] = -1e30f; sc[nf][3] = -1e30f; }
            }
        }

        // ---- online softmax (packed fp16 exp2) ----
        float mx0 = -1e30f, mx1 = -1e30f;
#pragma unroll
        for (int nf = 0; nf < 8; nf++) {
            mx0 = fmaxf(mx0, fmaxf(sc[nf][0], sc[nf][1]));
            mx1 = fmaxf(mx1, fmaxf(sc[nf][2], sc[nf][3]));
        }
        mx0 = fmaxf(mx0, __shfl_xor_sync(0xffffffffu, mx0, 1));
        mx0 = fmaxf(mx0, __shfl_xor_sync(0xffffffffu, mx0, 2));
        mx1 = fmaxf(mx1, __shfl_xor_sync(0xffffffffu, mx1, 1));
        mx1 = fmaxf(mx1, __shfl_xor_sync(0xffffffffu, mx1, 2));

        const float m0n = fmaxf(m0, mx0);
        const float m1n = fmaxf(m1, mx1);
        const float s0  = ex2(m0 - m0n);
        const float s1  = ex2(m1 - m1n);
        m0 = m0n; m1 = m1n;

        uint32_t pf[8][2];
#pragma unroll
        for (int nf = 0; nf < 8; nf++) {
            pf[nf][0] = ex2_h2(h2u(__floats2half2_rn(sc[nf][0] - m0n, sc[nf][1] - m0n)));
            pf[nf][1] = ex2_h2(h2u(__floats2half2_rn(sc[nf][2] - m1n, sc[nf][3] - m1n)));
        }

        // ---- l partials via HADD2 tree (fma pipe; tensor pipe freed) ----
        {
            __half2 a0 = __hadd2(__hadd2(u2h(pf[0][0]), u2h(pf[1][0])),
                                 __hadd2(u2h(pf[2][0]), u2h(pf[3][0])));
            __half2 a1 = __hadd2(__hadd2(u2h(pf[4][0]), u2h(pf[5][0])),
                                 __hadd2(u2h(pf[6][0]), u2h(pf[7][0])));
            __half2 b0 = __hadd2(__hadd2(u2h(pf[0][1]), u2h(pf[1][1])),
                                 __hadd2(u2h(pf[2][1]), u2h(pf[3][1])));
            __half2 b1 = __hadd2(__hadd2(u2h(pf[4][1]), u2h(pf[5][1])),
                                 __hadd2(u2h(pf[6][1]), u2h(pf[7][1])));
            float2 fa = __half22float2(__hadd2(a0, a1));
            float2 fb = __half22float2(__hadd2(b0, b1));
            l0 = l0 * s0 + (fa.x + fa.y);
            l1 = l1 * s1 + (fb.x + fb.y);
        }
#pragma unroll
        for (int nf = 0; nf < 8; nf++) {
            o[nf][0] *= s0; o[nf][1] *= s0;
            o[nf][2] *= s1; o[nf][3] *= s1;
        }

        // ---- O += P V ----
#pragma unroll
        for (int ks = 0; ks < 4; ks++) {
            uint32_t af[4];
            af[0] = pf[2 * ks][0];
            af[1] = pf[2 * ks][1];
            af[2] = pf[2 * ks + 1][0];
            af[3] = pf[2 * ks + 1][1];
            const uint32_t vrow = v_rowbase + bofs + ((uint32_t)ks << 11);
#pragma unroll
            for (int nfp = 0; nfp < 4; nfp++) {
                uint32_t r[4];
                ldsm_x4_trans(r, vrow + ((((uint32_t)nfp << 5) + v_cbit) ^ xr));
                mma_f16_16x8x16(o[2 * nfp    ], af, r    );
                mma_f16_16x8x16(o[2 * nfp + 1], af, r + 2);
            }
        }
    }

    // ---- epilogue: reduce l partials across t-lanes, normalize, store ----
    l0 += __shfl_xor_sync(0xffffffffu, l0, 1);
    l0 += __shfl_xor_sync(0xffffffffu, l0, 2);
    l1 += __shfl_xor_sync(0xffffffffu, l1, 1);
    l1 += __shfl_xor_sync(0xffffffffu, l1, 2);
    const float i0 = 1.f / l0;
    const float i1 = 1.f / l1;

    const int row0 = q0 + wr * 16 + g;
    __half* out0 = ctx + ((size_t)b * SEQQ + row0) * DMODEL + h * DHEAD;
    __half* out1 = out0 + (size_t)8 * DMODEL;
#pragma unroll
    for (int nf = 0; nf < 8; nf++) {
        const int col = nf * 8 + 2 * t;
        *(__half2*)(out0 + col) = __floats2half2_rn(o[nf][0] * i0, o[nf][1] * i0);
        *(__half2*)(out1 + col) = __floats2half2_rn(o[nf][2] * i1, o[nf][3] * i1);
    }
}

// =====================================================================
// launch
// =====================================================================
extern "C" void kernel_launch(void* const* d_in, const int* in_sizes, int n_in,
                              void* d_out, int out_size)
{
    const float* queries    = (const float*)d_in[0];
    const float* keys       = (const float*)d_in[1];
    const float* values     = (const float*)d_in[2];
    const int*   valid_lens = (const int*)  d_in[3];
    const float* W_q        = (const float*)d_in[4];
    const float* W_k        = (const float*)d_in[5];
    const float* W_v        = (const float*)d_in[6];
    const float* W_o        = (const float*)d_in[7];

    void *qp, *kp, *vp, *ctx;
    cudaGetSymbolAddress(&qp,  g_qph);
    cudaGetSymbolAddress(&kp,  g_kph);
    cudaGetSymbolAddress(&vp,  g_vph);
    cudaGetSymbolAddress(&ctx, g_ctxh);

    // pre-convert weights + inputs to fp16 (QSCALE folded into W_q)
    cvt_all<<<6656, 256>>>(queries, keys, values, W_q, W_k, W_v, W_o);

    dim3 gridQKV(DMODEL / 128, (BATCH * SEQQ) / 128, 3);   // (4, 64, 3)
    gemm_qkv<<<gridQKV, 256>>>((__half*)qp, (__half*)kp, (__half*)vp);

    dim3 gridF(SEQQ / 128, NBH);                           // (16, 32)
    flash_attn<<<gridF, 256>>>(valid_lens, (__half*)ctx);

    dim3 gridO(DMODEL / 128, (BATCH * SEQQ) / 128);        // (4, 64)
    gemm_out<<<gridO, 256>>>((const __half*)ctx, (float*)d_out);
}